// round 4
// baseline (speedup 1.0000x reference)
#include <cuda_runtime.h>

// Problem constants (fixed by the reference setup)
#define BZ_ 8
#define NF_ 10000
#define D_  16
#define H_  512
#define W_  512
#define HW_ (H_ * W_)        // 262144 = 2^18
#define NPIX (BZ_ * HW_)     // 2097152
#define CH_ (D_ + 1)         // 17 output channels
#define TPB 256
#define PPW 8                // pixels per warp per round (32 lanes / 4)
#define PPB ((TPB / 4) * 2)  // 128 pixels per block (2 per thread)

__global__ void __launch_bounds__(TPB)
render_kernel(const float4* __restrict__ attrs,   // [BZ*NF, 12] float4 (3 verts x 16 floats)
              const float*  __restrict__ baryw,   // [BZ, H, W, 3]
              const int*    __restrict__ tri,     // [BZ, H, W]
              float*        __restrict__ out)     // [BZ, 17, H, W]
{
    const int tid = threadIdx.x;
    const int q   = tid & 3;                       // which 4-channel slice I own
    const int p0  = blockIdx.x * PPB + (tid >> 2); // pixel A
    const int p1  = p0 + (TPB / 4);                // pixel B (independent chain)

    // ---- front-batched loads: maximize MLP ----
    const int tA = tri[p0];
    const int tB = tri[p1];

    const int iA = (tA < 0) ? 0 : tA;
    const int iB = (tB < 0) ? 0 : tB;

    // gathers: 64B-aligned 64B chunks -> warp-wide 8 lines per instruction
    const float4* vA = attrs + iA * 12 + q;
    const float4* vB = attrs + iB * 12 + q;
    const float4 aA = vA[0];
    const float4 bA = vA[4];
    const float4 cA = vA[8];
    const float4 aB = vB[0];
    const float4 bB = vB[4];
    const float4 cB = vB[8];

    float w0A = baryw[3 * p0 + 0];
    float w1A = baryw[3 * p0 + 1];
    float w2A = baryw[3 * p0 + 2];
    float w0B = baryw[3 * p1 + 0];
    float w1B = baryw[3 * p1 + 1];
    float w2B = baryw[3 * p1 + 2];

    // branchless background: zero weights -> zero output channels
    const float visA = (tA < 0) ? 0.0f : 1.0f;
    const float visB = (tB < 0) ? 0.0f : 1.0f;
    w0A *= visA; w1A *= visA; w2A *= visA;
    w0B *= visB; w1B *= visB; w2B *= visB;

    // ---- blend ----
    float4 rA, rB;
    rA.x = fmaf(w0A, aA.x, fmaf(w1A, bA.x, w2A * cA.x));
    rA.y = fmaf(w0A, aA.y, fmaf(w1A, bA.y, w2A * cA.y));
    rA.z = fmaf(w0A, aA.z, fmaf(w1A, bA.z, w2A * cA.z));
    rA.w = fmaf(w0A, aA.w, fmaf(w1A, bA.w, w2A * cA.w));
    rB.x = fmaf(w0B, aB.x, fmaf(w1B, bB.x, w2B * cB.x));
    rB.y = fmaf(w0B, aB.y, fmaf(w1B, bB.y, w2B * cB.y));
    rB.z = fmaf(w0B, aB.z, fmaf(w1B, bB.z, w2B * cB.z));
    rB.w = fmaf(w0B, aB.w, fmaf(w1B, bB.w, w2B * cB.w));

    // ---- stores ----
    {
        const int n   = p0 >> 18;                  // p0 / HW_
        const int pix = p0 & (HW_ - 1);
        float* outp = out + (size_t)n * CH_ * HW_ + pix + (size_t)(4 * q) * HW_;
        outp[(size_t)0 * HW_] = rA.x;
        outp[(size_t)1 * HW_] = rA.y;
        outp[(size_t)2 * HW_] = rA.z;
        outp[(size_t)3 * HW_] = rA.w;
        if (q == 0)
            out[(size_t)n * CH_ * HW_ + (size_t)D_ * HW_ + pix] = visA;
    }
    {
        const int n   = p1 >> 18;
        const int pix = p1 & (HW_ - 1);
        float* outp = out + (size_t)n * CH_ * HW_ + pix + (size_t)(4 * q) * HW_;
        outp[(size_t)0 * HW_] = rB.x;
        outp[(size_t)1 * HW_] = rB.y;
        outp[(size_t)2 * HW_] = rB.z;
        outp[(size_t)3 * HW_] = rB.w;
        if (q == 0)
            out[(size_t)n * CH_ * HW_ + (size_t)D_ * HW_ + pix] = visB;
    }
}

extern "C" void kernel_launch(void* const* d_in, const int* in_sizes, int n_in,
                              void* d_out, int out_size)
{
    const float4* attrs = (const float4*)d_in[0];
    const float*  baryw = (const float*)d_in[1];
    const int*    tri   = (const int*)d_in[2];
    float*        out   = (float*)d_out;

    render_kernel<<<NPIX / PPB, TPB>>>(attrs, baryw, tri, out);
}

// round 5
// speedup vs baseline: 1.6010x; 1.6010x over previous
#include <cuda_runtime.h>

// Problem constants (fixed by the reference setup)
#define BZ_ 8
#define NF_ 10000
#define D_  16
#define H_  512
#define W_  512
#define HW_ (H_ * W_)        // 262144 = 2^18
#define NPIX (BZ_ * HW_)     // 2097152
#define CH_ (D_ + 1)         // 17 output channels
#define TPB 256
#define PPB 256              // pixels per block: 8 warps x 32 px

__global__ void __launch_bounds__(TPB, 4)
render_kernel(const float4* __restrict__ attrs,   // [BZ*NF, 12] float4 (3 verts x 16 floats)
              const float*  __restrict__ baryw,   // [BZ, H, W, 3]
              const int*    __restrict__ tri,     // [BZ, H, W]
              float*        __restrict__ out)     // [BZ, 17, H, W]
{
    const int lane = threadIdx.x & 31;
    const int q    = lane & 3;                     // channel slice 4q..4q+3
    const int g    = lane >> 2;                    // pixel group within warp
    const int warp = threadIdx.x >> 5;
    const int base = blockIdx.x * PPB + warp * 32; // warp's first pixel (mult of 32)
    const int p0   = base + 4 * g;                 // my 4 consecutive pixels

    // ---- coalesced meta loads ----
    const int4 t4 = *(const int4*)(tri + p0);                      // 4 triangle ids
    const float4* bb = (const float4*)(baryw + 3 * p0);            // 12 floats, 16B aligned
    const float4 b0 = bb[0], b1 = bb[1], b2 = bb[2];

    const int ta[4] = { t4.x, t4.y, t4.z, t4.w };
    // per-slot barycentric weights (flat [px][3] layout)
    const float w0s[4] = { b0.x, b0.w, b1.z, b2.y };
    const float w1s[4] = { b0.y, b1.x, b1.w, b2.z };
    const float w2s[4] = { b0.z, b1.y, b2.x, b2.w };

    float4 acc[4];
    float  vis[4];

    #pragma unroll
    for (int s = 0; s < 4; s++) {
        const int t  = ta[s];
        const float v = (t < 0) ? 0.0f : 1.0f;
        const int  it = (t < 0) ? 0 : t;
        vis[s] = v;

        // my 64B-aligned 16B chunks of this face (1 line per 8 faces per instr)
        const float4* vp = attrs + it * 12 + q;
        const float4 a = vp[0];
        const float4 b = vp[4];
        const float4 c = vp[8];

        const float w0 = w0s[s] * v;
        const float w1 = w1s[s] * v;
        const float w2 = w2s[s] * v;

        float4 r;
        r.x = fmaf(w0, a.x, fmaf(w1, b.x, w2 * c.x));
        r.y = fmaf(w0, a.y, fmaf(w1, b.y, w2 * c.y));
        r.z = fmaf(w0, a.z, fmaf(w1, b.z, w2 * c.z));
        r.w = fmaf(w0, a.w, fmaf(w1, b.w, w2 * c.w));
        acc[s] = r;
    }

    // ---- stores: register transpose -> one STG.128 per channel (single plane) ----
    const int n    = base >> 18;                   // base / HW_
    const int pix0 = (base & (HW_ - 1)) + 4 * g;
    float* op = out + (size_t)n * CH_ * HW_ + pix0;

    float4 s0 = make_float4(acc[0].x, acc[1].x, acc[2].x, acc[3].x);
    float4 s1 = make_float4(acc[0].y, acc[1].y, acc[2].y, acc[3].y);
    float4 s2 = make_float4(acc[0].z, acc[1].z, acc[2].z, acc[3].z);
    float4 s3 = make_float4(acc[0].w, acc[1].w, acc[2].w, acc[3].w);

    *(float4*)(op + (size_t)(4 * q + 0) * HW_) = s0;
    *(float4*)(op + (size_t)(4 * q + 1) * HW_) = s1;
    *(float4*)(op + (size_t)(4 * q + 2) * HW_) = s2;
    *(float4*)(op + (size_t)(4 * q + 3) * HW_) = s3;

    if (q == 0)
        *(float4*)(op + (size_t)D_ * HW_) =
            make_float4(vis[0], vis[1], vis[2], vis[3]);   // visibility channel
}

extern "C" void kernel_launch(void* const* d_in, const int* in_sizes, int n_in,
                              void* d_out, int out_size)
{
    const float4* attrs = (const float4*)d_in[0];
    const float*  baryw = (const float*)d_in[1];
    const int*    tri   = (const int*)d_in[2];
    float*        out   = (float*)d_out;

    render_kernel<<<NPIX / PPB, TPB>>>(attrs, baryw, tri, out);
}